// round 7
// baseline (speedup 1.0000x reference)
#include <cuda_runtime.h>

// NCELoss: N=4096, E=1024, K=50 noise (+1 target). Output: scalar f32 loss.
//
// Single fused kernel, vocab-phased for L2 fit:
//   Each block (one example) partitions its 51 columns by weight-row index
//   into phase A (idx < V/2) and phase B (idx >= V/2), separated by a
//   __syncthreads. Blocks advance through phases roughly together, so the
//   live weight working set per phase is ~101 MB < 126 MB L2 -> repeat row
//   touches hit L2 (measured -40% DRAM bytes with this phasing in R6).
//   Inner loop is the proven best shape: full row, 8x LDG.128 per warp.
//   Last block (atomic ticket, self-resetting) reduces partials in double.

#define EDIM 1024
#define KNOISE 50
#define NCOLS (KNOISE + 1)
#define NORM_TERM 9.0f
#define NWARPS 8
#define MAXN 8192

__device__ double        g_partial[MAXN];
__device__ unsigned int  g_done = 0;

__device__ __forceinline__ float loss_term(int j, int idx, float s,
                                           const float* __restrict__ bias,
                                           const float* __restrict__ noise)
{
    const float logit = s + __ldg(&bias[idx]);
    const float p  = expf(logit - NORM_TERM);
    const float kp = (float)KNOISE * __ldg(&noise[idx]);
    const float num = (j == 0) ? p : kp;   // j==0: data term, else noise term
    return logf(num / (p + kp));
}

__global__ __launch_bounds__(NWARPS * 32) void nce_loss_kernel(
    const float* __restrict__ input,
    const int*   __restrict__ target,
    const int*   __restrict__ noise_samples,
    const float* __restrict__ noise,
    const float* __restrict__ weight,
    const float* __restrict__ bias,
    float*       __restrict__ out,
    int N, int vhalf)
{
    __shared__ float4   s_in[EDIM / 4];     // 4 KB input row
    __shared__ unsigned s_list[NCOLS];      // (idx << 6) | j, A-phase first
    __shared__ int      s_cntA[2];
    __shared__ float    s_wsum[NWARPS];
    __shared__ bool     s_is_last;

    const int n    = blockIdx.x;
    const int tid  = threadIdx.x;
    const int lane = tid & 31;
    const int wid  = tid >> 5;

    // Stage input row: 256 float4 across 256 threads.
    s_in[tid] = reinterpret_cast<const float4*>(input + (size_t)n * EDIM)[tid];

    // Partition the 51 columns by idx < vhalf (two warps, ballot-based).
    bool     pred = false;
    unsigned b = 0, bv = 0;
    int      myidx = 0;
    if (tid < 64) {
        const bool valid = tid < NCOLS;
        if (valid)
            myidx = (tid == 0) ? __ldg(&target[n])
                               : __ldg(&noise_samples[n * KNOISE + tid - 1]);
        pred = valid && (myidx < vhalf);
        b  = __ballot_sync(0xffffffffu, pred);
        bv = __ballot_sync(0xffffffffu, valid);
        if (lane == 0) s_cntA[wid] = __popc(b);
    }
    __syncthreads();

    const int cA = s_cntA[0] + s_cntA[1];
    if (tid < 64 && tid < NCOLS) {
        const unsigned lt  = (1u << lane) - 1u;
        const int posA = __popc(b & lt);
        const int posB = __popc(~b & bv & lt);
        const int Aoff = (tid >= 32) ? s_cntA[0] : 0;
        const int Boff = (tid >= 32) ? (32 - s_cntA[0]) : 0;
        const int pos  = pred ? (Aoff + posA) : (cA + Boff + posB);
        s_list[pos] = ((unsigned)myidx << 6) | (unsigned)tid;
    }
    __syncthreads();

    // Two phases: entries [0, cA) then [cA, NCOLS). Inner loop: one column,
    // 8x LDG.128 front-batched per warp (MLP_p1 = 8).
    float acc = 0.0f;
    #pragma unroll 1
    for (int phase = 0; phase < 2; phase++) {
        const int lo = phase ? cA : 0;
        const int hi = phase ? NCOLS : cA;
        #pragma unroll 1
        for (int e = lo + wid; e < hi; e += NWARPS) {
            const unsigned ent = s_list[e];
            const int j   = (int)(ent & 63u);
            const int idx = (int)(ent >> 6);
            const float4* w4 = reinterpret_cast<const float4*>(
                weight + (size_t)idx * EDIM);

            float4 w[8];
            #pragma unroll
            for (int i = 0; i < 8; i++) w[i] = __ldg(&w4[lane + 32 * i]);

            float s = 0.0f;
            #pragma unroll
            for (int i = 0; i < 8; i++) {
                const float4 x = s_in[lane + 32 * i];
                s += w[i].x * x.x + w[i].y * x.y + w[i].z * x.z + w[i].w * x.w;
            }
            #pragma unroll
            for (int o = 16; o; o >>= 1) s += __shfl_xor_sync(0xffffffffu, s, o);

            if (lane == 0) acc += loss_term(j, idx, s, bias, noise);
        }
        __syncthreads();   // keep blocks phase-aligned chip-wide
    }

    if (lane == 0) s_wsum[wid] = acc;
    __syncthreads();

    if (wid == 0) {
        float v = (lane < NWARPS) ? s_wsum[lane] : 0.0f;
        #pragma unroll
        for (int o = NWARPS / 2; o; o >>= 1) v += __shfl_xor_sync(0xffffffffu, v, o);
        if (lane == 0) g_partial[n] = (double)v;
    }

    // Completion ticket: last block reduces all partials (fixed order, double).
    if (tid == 0) {
        __threadfence();
        unsigned int prev = atomicAdd(&g_done, 1u);
        s_is_last = (prev == (unsigned int)(gridDim.x - 1));
    }
    __syncthreads();

    if (s_is_last) {
        double d = 0.0;
        for (int i = tid; i < N; i += NWARPS * 32) {
            double val;
            asm volatile("ld.global.cg.f64 %0, [%1];"
                         : "=d"(val) : "l"(g_partial + i));
            d += val;
        }
        #pragma unroll
        for (int o = 16; o; o >>= 1) d += __shfl_xor_sync(0xffffffffu, d, o);
        __shared__ double s_dsum[NWARPS];
        if (lane == 0) s_dsum[wid] = d;
        __syncthreads();
        if (wid == 0) {
            double t = (lane < NWARPS) ? s_dsum[lane] : 0.0;
            #pragma unroll
            for (int o = NWARPS / 2; o; o >>= 1)
                t += __shfl_xor_sync(0xffffffffu, t, o);
            if (lane == 0) {
                out[0] = (float)(-t / (double)N);
                g_done = 0u;                      // reset for graph replay
            }
        }
    }
}

extern "C" void kernel_launch(void* const* d_in, const int* in_sizes, int n_in,
                              void* d_out, int out_size) {
    const float* input         = (const float*)d_in[0];
    const int*   target        = (const int*)  d_in[1];
    const int*   noise_samples = (const int*)  d_in[2];
    const float* noise         = (const float*)d_in[3];
    const float* weight        = (const float*)d_in[4];
    const float* bias          = (const float*)d_in[5];
    float* out = (float*)d_out;

    const int N = in_sizes[1];   // number of examples
    const int V = in_sizes[3];   // vocab size (noise array length)

    nce_loss_kernel<<<N, NWARPS * 32>>>(input, target, noise_samples, noise,
                                        weight, bias, out, N, V / 2);
}

// round 8
// speedup vs baseline: 1.0760x; 1.0760x over previous
#include <cuda_runtime.h>

// NCELoss: N=4096, E=1024, K=50 noise (+1 target). Output: scalar f32 loss.
//
// Persistent single kernel, E-split into two phases separated by a software
// grid barrier (grid sized for guaranteed residency via __launch_bounds__):
//   phase 0: dots over weight[:,0:512]  -> g_logit[n][j]
//   phase 1: dots over weight[:,512:1024] + g_logit -> loss -> block partial
// Guaranteed global phase separation keeps the live weight working set at
// ~99 MB < 126 MB L2, so repeat row touches hit L2 (R6 measured -40% DRAM
// bytes from this separation; R7 showed block-local phasing does nothing).
// g_logit is written and read by the SAME block, so the barrier is a pure
// performance fence - correctness never depends on it.
// Last block (ticket) reduces the 888 block partials in double; all global
// state self-resets so the kernel is graph-replay safe.

#define EDIM   1024
#define HALF   512
#define KNOISE 50
#define NCOLS  (KNOISE + 1)
#define NORM_TERM 9.0f
#define NWARPS 8
#define NTHREADS (NWARPS * 32)
#define MAXN   8192
#define GRID_BLOCKS 888            // 148 SMs x 6 resident blocks (guaranteed)

__device__ float         g_logit[MAXN * NCOLS];
__device__ double        g_partial[GRID_BLOCKS];
__device__ unsigned int  g_bar  = 0;    // phase barrier counter
__device__ unsigned int  g_done = 0;    // completion ticket

__device__ __forceinline__ float loss_term(int j, int idx, float s,
                                           const float* __restrict__ bias,
                                           const float* __restrict__ noise)
{
    const float logit = s + __ldg(&bias[idx]);
    const float p  = expf(logit - NORM_TERM);
    const float kp = (float)KNOISE * __ldg(&noise[idx]);
    const float num = (j == 0) ? p : kp;   // j==0: data term, else noise term
    return logf(num / (p + kp));
}

// Warp-collective dot of a 512-float weight chunk vs smem input chunk.
__device__ __forceinline__ float dot512(const float* __restrict__ wchunk,
                                        const float4* __restrict__ s_in,
                                        int lane)
{
    const float4* w4 = reinterpret_cast<const float4*>(wchunk);
    float4 w[4];
    #pragma unroll
    for (int i = 0; i < 4; i++) w[i] = __ldg(&w4[lane + 32 * i]);
    float s = 0.0f;
    #pragma unroll
    for (int i = 0; i < 4; i++) {
        const float4 x = s_in[lane + 32 * i];
        s += w[i].x * x.x + w[i].y * x.y + w[i].z * x.z + w[i].w * x.w;
    }
    return s;
}

__global__ __launch_bounds__(NTHREADS, 6) void nce_loss_kernel(
    const float* __restrict__ input,
    const int*   __restrict__ target,
    const int*   __restrict__ noise_samples,
    const float* __restrict__ noise,
    const float* __restrict__ weight,
    const float* __restrict__ bias,
    float*       __restrict__ out,
    int N)
{
    __shared__ float4 s_in[HALF / 4];      // 2 KB input half-row
    __shared__ float  s_wsum[NWARPS];
    __shared__ bool   s_is_last;

    const int tid  = threadIdx.x;
    const int lane = tid & 31;
    const int wid  = tid >> 5;

    float acc = 0.0f;                      // phase-1 loss accumulator (lane 0s)

    #pragma unroll 1
    for (int half = 0; half < 2; half++) {
        const int eoff = half * HALF;

        #pragma unroll 1
        for (int n = blockIdx.x; n < N; n += gridDim.x) {
            // Stage this example's input half-row.
            const float4* in4 = reinterpret_cast<const float4*>(
                input + (size_t)n * EDIM + eoff);
            for (int i = tid; i < HALF / 4; i += NTHREADS) s_in[i] = in4[i];
            __syncthreads();

            // Columns in pairs (j, j+8): 8 LDG.128 in flight per warp.
            #pragma unroll 1
            for (int j = wid; j < NCOLS; j += 2 * NWARPS) {
                const int  jB   = j + NWARPS;
                const bool hasB = (jB < NCOLS);

                const int idxA = (j == 0)
                    ? __ldg(&target[n])
                    : __ldg(&noise_samples[n * KNOISE + (j - 1)]);
                const int idxB = hasB
                    ? __ldg(&noise_samples[n * KNOISE + (jB - 1)]) : idxA;

                float sA = dot512(weight + (size_t)idxA * EDIM + eoff, s_in, lane);
                float sB = hasB
                    ? dot512(weight + (size_t)idxB * EDIM + eoff, s_in, lane)
                    : 0.0f;

                #pragma unroll
                for (int o = 16; o; o >>= 1) {
                    sA += __shfl_xor_sync(0xffffffffu, sA, o);
                    sB += __shfl_xor_sync(0xffffffffu, sB, o);
                }

                if (lane == 0) {
                    if (half == 0) {
                        g_logit[n * NCOLS + j] = sA;
                        if (hasB) g_logit[n * NCOLS + jB] = sB;
                    } else {
                        acc += loss_term(j, idxA, g_logit[n * NCOLS + j] + sA,
                                         bias, noise);
                        if (hasB)
                            acc += loss_term(jB, idxB,
                                             g_logit[n * NCOLS + jB] + sB,
                                             bias, noise);
                    }
                }
            }
            __syncthreads();               // s_in reused next example
        }

        // Global phase barrier (performance fence only; grid is resident).
        if (half == 0) {
            if (tid == 0) {
                atomicAdd(&g_bar, 1u);
                while (true) {
                    unsigned int v;
                    asm volatile("ld.global.cg.u32 %0, [%1];"
                                 : "=r"(v) : "l"(&g_bar));
                    if (v >= gridDim.x) break;
                    __nanosleep(128);
                }
            }
            __syncthreads();
        }
    }

    // Block partial -> global.
    if (lane == 0) s_wsum[wid] = acc;
    __syncthreads();
    if (wid == 0) {
        float v = (lane < NWARPS) ? s_wsum[lane] : 0.0f;
        #pragma unroll
        for (int o = NWARPS / 2; o; o >>= 1) v += __shfl_xor_sync(0xffffffffu, v, o);
        if (lane == 0) g_partial[blockIdx.x] = (double)v;
    }

    // Completion ticket: last block reduces, writes out, resets state.
    if (tid == 0) {
        __threadfence();
        unsigned int prev = atomicAdd(&g_done, 1u);
        s_is_last = (prev == gridDim.x - 1);
    }
    __syncthreads();

    if (s_is_last) {
        double d = 0.0;
        for (int i = tid; i < (int)gridDim.x; i += NTHREADS) {
            double val;
            asm volatile("ld.global.cg.f64 %0, [%1];"
                         : "=d"(val) : "l"(g_partial + i));
            d += val;
        }
        #pragma unroll
        for (int o = 16; o; o >>= 1) d += __shfl_xor_sync(0xffffffffu, d, o);
        __shared__ double s_dsum[NWARPS];
        if (lane == 0) s_dsum[wid] = d;
        __syncthreads();
        if (wid == 0) {
            double t = (lane < NWARPS) ? s_dsum[lane] : 0.0;
            #pragma unroll
            for (int o = NWARPS / 2; o; o >>= 1)
                t += __shfl_xor_sync(0xffffffffu, t, o);
            if (lane == 0) {
                out[0]  = (float)(-t / (double)N);
                g_done  = 0u;               // reset for graph replay
                g_bar   = 0u;
            }
        }
    }
}

extern "C" void kernel_launch(void* const* d_in, const int* in_sizes, int n_in,
                              void* d_out, int out_size) {
    const float* input         = (const float*)d_in[0];
    const int*   target        = (const int*)  d_in[1];
    const int*   noise_samples = (const int*)  d_in[2];
    const float* noise         = (const float*)d_in[3];
    const float* weight        = (const float*)d_in[4];
    const float* bias          = (const float*)d_in[5];
    float* out = (float*)d_out;

    const int N = in_sizes[1];  // number of examples

    int grid = GRID_BLOCKS;
    if (grid > N) grid = N;

    nce_loss_kernel<<<grid, NTHREADS>>>(input, target, noise_samples, noise,
                                        weight, bias, out, N);
}